// round 14
// baseline (speedup 1.0000x reference)
#include <cuda_runtime.h>
#include <cstdint>

#define N_NODES  50000
#define N_EDGES  800000
#define D_IN     128
#define D_HID    256
#define N_GRAPHS 256
#define NT       256

#define N_MTILES ((N_NODES + 127) / 128)       // 391
#define N_GT     (N_MTILES * 2)                // 782 gemm tiles
#define N_CH_L1  (N_NODES / 8)                 // 6250 chunks (8 nodes, full 128-col row)
#define N_CH_L2  (N_NODES / 8 * 2)             // 12500 chunks (8 nodes x half-row)

typedef unsigned long long ull;

// ---------------- scratch (device globals; no runtime allocation) ----------------
__device__ float g_agg1[N_NODES * D_IN];
__device__ float g_h1  [N_NODES * D_HID];
__device__ float g_agg2[N_NODES * D_HID];
__device__ float g_h2  [N_NODES * D_HID];
__device__ int   g_cnt [N_NODES];
__device__ int   g_row [N_NODES + 1];
__device__ int   g_cur [N_NODES];
__device__ int   g_col [N_EDGES];
__device__ int   g_bagg[512];
__device__ int   g_bpref[512];
__device__ int   g_barrier_ctr;
__device__ int   g_wq[4];
__device__ int   g_idx64;

// ---------------- packed f32x2 helpers ----------------
__device__ __forceinline__ ull pack2(float lo, float hi) {
    ull r;
    asm("mov.b64 %0, {%1, %2};" : "=l"(r) : "f"(lo), "f"(hi));
    return r;
}
__device__ __forceinline__ void unpack2(ull v, float& lo, float& hi) {
    asm("mov.b64 {%0, %1}, %2;" : "=f"(lo), "=f"(hi) : "l"(v));
}
__device__ __forceinline__ ull fma2(ull a, ull b, ull c) {
    ull r;
    asm("fma.rn.f32x2 %0, %1, %2, %3;" : "=l"(r) : "l"(a), "l"(b), "l"(c));
    return r;
}

__device__ __forceinline__ int load_idx_(const void* p, int i, int i64) {
    if (i64) return (int)((const long long*)p)[i];
    return ((const int*)p)[i];
}

// ---------------- shared memory union ----------------
struct SmemGemm { float As[2][16][132]; float Bs[2][16][132]; int tile; };
struct SmemScan { int wsum[32]; };
struct SmemPool { float r0[NT]; float r1[NT]; };
union SmemAll { SmemGemm g; SmemScan s; SmemPool p; };

// ---------------- grid barrier (all gridDim.x blocks resident) --------------------
__device__ __forceinline__ void gridbar(int target) {
    __syncthreads();
    if (threadIdx.x == 0) {
        __threadfence();
        atomicAdd(&g_barrier_ctr, 1);
        while (*(volatile int*)&g_barrier_ctr < target) { __nanosleep(64); }
    }
    __syncthreads();
}

// ---------------- prep kernel ----------------
__global__ void reset_kernel(const int* __restrict__ ei) {
    int i = blockIdx.x * blockDim.x + threadIdx.x;
    if (i == 0) {
        g_barrier_ctr = 0;
#pragma unroll
        for (int q = 0; q < 4; q++) g_wq[q] = 0;
        int any = 0;
#pragma unroll
        for (int j = 1; j < 256; j += 2) any |= ei[j];
        g_idx64 = (any == 0) ? 1 : 0;
    }
    for (; i < N_NODES; i += gridDim.x * blockDim.x) g_cnt[i] = 0;
}

// ---------------- block-wide exclusive scan over 256 thread values ----------------
__device__ int block_scan_excl(int v, SmemScan& ss, int& total) {
    int lane = threadIdx.x & 31, w = threadIdx.x >> 5;
    int s = v;
#pragma unroll
    for (int o = 1; o < 32; o <<= 1) {
        int u = __shfl_up_sync(0xffffffffu, s, o);
        if (lane >= o) s += u;
    }
    if (lane == 31) ss.wsum[w] = s;
    __syncthreads();
    if (w == 0) {
        int ws = (lane < 8) ? ss.wsum[lane] : 0;
#pragma unroll
        for (int o = 1; o < 8; o <<= 1) {
            int u = __shfl_up_sync(0xffffffffu, ws, o);
            if (lane >= o) ws += u;
        }
        if (lane < 8) ss.wsum[lane] = ws;
    }
    __syncthreads();
    int incl = s + (w > 0 ? ss.wsum[w - 1] : 0);
    total = ss.wsum[7];
    return incl - v;
}

// ---------------- per-warp gather of one node-segment (128 cols), MLP-8 -----------
// STRIDE4 = row stride in float4 units (32 for D=128, 64 for D=256); soff = segment
// offset in float4 units. Batch-8 index prefetch keeps 8 row loads in flight.
template<int STRIDE4>
__device__ __forceinline__ void gather_node_seg(int node, const float* __restrict__ x,
                                                float* __restrict__ agg, int lane, int soff) {
    int beg = g_row[node], end = g_row[node + 1];
    const float4* xb = (const float4*)x;
    float4 a = make_float4(0.f, 0.f, 0.f, 0.f);

    int p = beg;
    int c[8];
    if (p + 8 <= end) {
#pragma unroll
        for (int i = 0; i < 8; i++) c[i] = g_col[p + i];
    }
    while (p + 8 <= end) {
        int n0 = c[0], n1 = c[1], n2 = c[2], n3 = c[3];
        int n4 = c[4], n5 = c[5], n6 = c[6], n7 = c[7];
        int pn = p + 8;
        if (pn + 8 <= end) {
#pragma unroll
            for (int i = 0; i < 8; i++) c[i] = g_col[pn + i];
        }
        float4 v0 = xb[(size_t)n0 * STRIDE4 + soff + lane];
        float4 v1 = xb[(size_t)n1 * STRIDE4 + soff + lane];
        float4 v2 = xb[(size_t)n2 * STRIDE4 + soff + lane];
        float4 v3 = xb[(size_t)n3 * STRIDE4 + soff + lane];
        float4 v4 = xb[(size_t)n4 * STRIDE4 + soff + lane];
        float4 v5 = xb[(size_t)n5 * STRIDE4 + soff + lane];
        float4 v6 = xb[(size_t)n6 * STRIDE4 + soff + lane];
        float4 v7 = xb[(size_t)n7 * STRIDE4 + soff + lane];
        a.x += ((v0.x + v1.x) + (v2.x + v3.x)) + ((v4.x + v5.x) + (v6.x + v7.x));
        a.y += ((v0.y + v1.y) + (v2.y + v3.y)) + ((v4.y + v5.y) + (v6.y + v7.y));
        a.z += ((v0.z + v1.z) + (v2.z + v3.z)) + ((v4.z + v5.z) + (v6.z + v7.z));
        a.w += ((v0.w + v1.w) + (v2.w + v3.w)) + ((v4.w + v5.w) + (v6.w + v7.w));
        p = pn;
    }
    if (p + 4 <= end) {
        int n0 = g_col[p], n1 = g_col[p + 1], n2 = g_col[p + 2], n3 = g_col[p + 3];
        float4 v0 = xb[(size_t)n0 * STRIDE4 + soff + lane];
        float4 v1 = xb[(size_t)n1 * STRIDE4 + soff + lane];
        float4 v2 = xb[(size_t)n2 * STRIDE4 + soff + lane];
        float4 v3 = xb[(size_t)n3 * STRIDE4 + soff + lane];
        a.x += (v0.x + v1.x) + (v2.x + v3.x);
        a.y += (v0.y + v1.y) + (v2.y + v3.y);
        a.z += (v0.z + v1.z) + (v2.z + v3.z);
        a.w += (v0.w + v1.w) + (v2.w + v3.w);
        p += 4;
    }
    for (; p < end; p++) {
        int s0 = g_col[p];
        float4 v0 = xb[(size_t)s0 * STRIDE4 + soff + lane];
        a.x += v0.x; a.y += v0.y; a.z += v0.z; a.w += v0.w;
    }
    ((float4*)agg)[(size_t)node * STRIDE4 + soff + lane] = a;
}

// ---------------- gather stage: warp-granular work stealing over segments ---------
template<int STRIDE4>
__device__ void gather_stage(int* wq, int nch, const float* __restrict__ x,
                             float* __restrict__ agg) {
    int lane = threadIdx.x & 31;
    while (true) {
        int ch;
        if (lane == 0) ch = atomicAdd(wq, 1);
        ch = __shfl_sync(0xffffffffu, ch, 0);
        if (ch >= nch) break;
        int seg, nbase;
        if (STRIDE4 == 32) { seg = 0; nbase = ch * 8; }
        else               { seg = ch & 1; nbase = (ch >> 1) * 8; }
        int soff = seg * 32;
#pragma unroll 1
        for (int k = 0; k < 8; k++)
            gather_node_seg<STRIDE4>(nbase + k, x, agg, lane, soff);
    }
}

// ---------------- gemm stage: C = relu(A1@W1^T + A2@W2^T + bias) ------------------
// 128x128 tiles, BK=16, f32x2 packed FMA, work-stealing tile scheduler.
template<int K>
__device__ void gemm_stage(const float* __restrict__ A1, const float* __restrict__ W1,
                           const float* __restrict__ A2, const float* __restrict__ W2,
                           const float* __restrict__ bias, float* __restrict__ C,
                           SmemGemm& sm, int* wq) {
    constexpr int BK = 16;
    constexpr int T = K / BK;
    int tid = threadIdx.x;
    int tx = tid & 15;
    int ty = tid >> 4;
    int lm = tid >> 2;
    int lk = (tid & 3) * 4;
    const float4 z4 = make_float4(0.f, 0.f, 0.f, 0.f);

    while (true) {
        if (tid == 0) sm.tile = atomicAdd(wq, 1);
        __syncthreads();
        int tile = sm.tile;
        if (tile >= N_GT) break;
        int bm = (tile >> 1) * 128;
        int bn = (tile & 1) * 128;

        ull acc[8][4];
#pragma unroll
        for (int i = 0; i < 8; i++)
#pragma unroll
            for (int j = 0; j < 4; j++) acc[i][j] = pack2(0.f, 0.f);

#pragma unroll 1
        for (int phase = 0; phase < 2; phase++) {
            const float* A = phase ? A2 : A1;
            const float* W = phase ? W2 : W1;

            float4 ra0, ra1, rb0, rb1;
            {
                int r0 = bm + lm, r1 = bm + lm + 64;
                ra0 = (r0 < N_NODES) ? *(const float4*)(A + (size_t)r0 * K + lk) : z4;
                ra1 = (r1 < N_NODES) ? *(const float4*)(A + (size_t)r1 * K + lk) : z4;
                rb0 = *(const float4*)(W + (size_t)(bn + lm) * K + lk);
                rb1 = *(const float4*)(W + (size_t)(bn + lm + 64) * K + lk);
                sm.As[0][lk + 0][lm] = ra0.x; sm.As[0][lk + 1][lm] = ra0.y;
                sm.As[0][lk + 2][lm] = ra0.z; sm.As[0][lk + 3][lm] = ra0.w;
                sm.As[0][lk + 0][lm + 64] = ra1.x; sm.As[0][lk + 1][lm + 64] = ra1.y;
                sm.As[0][lk + 2][lm + 64] = ra1.z; sm.As[0][lk + 3][lm + 64] = ra1.w;
                sm.Bs[0][lk + 0][lm] = rb0.x; sm.Bs[0][lk + 1][lm] = rb0.y;
                sm.Bs[0][lk + 2][lm] = rb0.z; sm.Bs[0][lk + 3][lm] = rb0.w;
                sm.Bs[0][lk + 0][lm + 64] = rb1.x; sm.Bs[0][lk + 1][lm + 64] = rb1.y;
                sm.Bs[0][lk + 2][lm + 64] = rb1.z; sm.Bs[0][lk + 3][lm + 64] = rb1.w;
            }
            __syncthreads();

#pragma unroll 1
            for (int t = 0; t < T; t++) {
                int cur = t & 1, nxt = cur ^ 1;
                if (t + 1 < T) {
                    int k0 = (t + 1) * BK;
                    int r0 = bm + lm, r1 = bm + lm + 64;
                    ra0 = (r0 < N_NODES) ? *(const float4*)(A + (size_t)r0 * K + k0 + lk) : z4;
                    ra1 = (r1 < N_NODES) ? *(const float4*)(A + (size_t)r1 * K + k0 + lk) : z4;
                    rb0 = *(const float4*)(W + (size_t)(bn + lm) * K + k0 + lk);
                    rb1 = *(const float4*)(W + (size_t)(bn + lm + 64) * K + k0 + lk);
                }
#pragma unroll
                for (int k = 0; k < BK; k++) {
                    float4 av0 = *(const float4*)&sm.As[cur][k][ty * 8];
                    float4 av1 = *(const float4*)&sm.As[cur][k][ty * 8 + 4];
                    float4 bv0 = *(const float4*)&sm.Bs[cur][k][tx * 4];
                    float4 bv1 = *(const float4*)&sm.Bs[cur][k][64 + tx * 4];
                    ull b0 = pack2(bv0.x, bv0.y);
                    ull b1 = pack2(bv0.z, bv0.w);
                    ull b2 = pack2(bv1.x, bv1.y);
                    ull b3 = pack2(bv1.z, bv1.w);
                    ull ad;
                    ad = pack2(av0.x, av0.x);
                    acc[0][0] = fma2(ad, b0, acc[0][0]); acc[0][1] = fma2(ad, b1, acc[0][1]);
                    acc[0][2] = fma2(ad, b2, acc[0][2]); acc[0][3] = fma2(ad, b3, acc[0][3]);
                    ad = pack2(av0.y, av0.y);
                    acc[1][0] = fma2(ad, b0, acc[1][0]); acc[1][1] = fma2(ad, b1, acc[1][1]);
                    acc[1][2] = fma2(ad, b2, acc[1][2]); acc[1][3] = fma2(ad, b3, acc[1][3]);
                    ad = pack2(av0.z, av0.z);
                    acc[2][0] = fma2(ad, b0, acc[2][0]); acc[2][1] = fma2(ad, b1, acc[2][1]);
                    acc[2][2] = fma2(ad, b2, acc[2][2]); acc[2][3] = fma2(ad, b3, acc[2][3]);
                    ad = pack2(av0.w, av0.w);
                    acc[3][0] = fma2(ad, b0, acc[3][0]); acc[3][1] = fma2(ad, b1, acc[3][1]);
                    acc[3][2] = fma2(ad, b2, acc[3][2]); acc[3][3] = fma2(ad, b3, acc[3][3]);
                    ad = pack2(av1.x, av1.x);
                    acc[4][0] = fma2(ad, b0, acc[4][0]); acc[4][1] = fma2(ad, b1, acc[4][1]);
                    acc[4][2] = fma2(ad, b2, acc[4][2]); acc[4][3] = fma2(ad, b3, acc[4][3]);
                    ad = pack2(av1.y, av1.y);
                    acc[5][0] = fma2(ad, b0, acc[5][0]); acc[5][1] = fma2(ad, b1, acc[5][1]);
                    acc[5][2] = fma2(ad, b2, acc[5][2]); acc[5][3] = fma2(ad, b3, acc[5][3]);
                    ad = pack2(av1.z, av1.z);
                    acc[6][0] = fma2(ad, b0, acc[6][0]); acc[6][1] = fma2(ad, b1, acc[6][1]);
                    acc[6][2] = fma2(ad, b2, acc[6][2]); acc[6][3] = fma2(ad, b3, acc[6][3]);
                    ad = pack2(av1.w, av1.w);
                    acc[7][0] = fma2(ad, b0, acc[7][0]); acc[7][1] = fma2(ad, b1, acc[7][1]);
                    acc[7][2] = fma2(ad, b2, acc[7][2]); acc[7][3] = fma2(ad, b3, acc[7][3]);
                }
                if (t + 1 < T) {
                    sm.As[nxt][lk + 0][lm] = ra0.x; sm.As[nxt][lk + 1][lm] = ra0.y;
                    sm.As[nxt][lk + 2][lm] = ra0.z; sm.As[nxt][lk + 3][lm] = ra0.w;
                    sm.As[nxt][lk + 0][lm + 64] = ra1.x; sm.As[nxt][lk + 1][lm + 64] = ra1.y;
                    sm.As[nxt][lk + 2][lm + 64] = ra1.z; sm.As[nxt][lk + 3][lm + 64] = ra1.w;
                    sm.Bs[nxt][lk + 0][lm] = rb0.x; sm.Bs[nxt][lk + 1][lm] = rb0.y;
                    sm.Bs[nxt][lk + 2][lm] = rb0.z; sm.Bs[nxt][lk + 3][lm] = rb0.w;
                    sm.Bs[nxt][lk + 0][lm + 64] = rb1.x; sm.Bs[nxt][lk + 1][lm + 64] = rb1.y;
                    sm.Bs[nxt][lk + 2][lm + 64] = rb1.z; sm.Bs[nxt][lk + 3][lm + 64] = rb1.w;
                }
                __syncthreads();
            }
            __syncthreads();
        }

        // epilogue: bias + relu
        float4 bb0 = *(const float4*)(bias + bn + tx * 4);
        float4 bb1 = *(const float4*)(bias + bn + 64 + tx * 4);
#pragma unroll
        for (int i = 0; i < 8; i++) {
            int row = bm + ty * 8 + i;
            if (row < N_NODES) {
                float c0, c1, c2, c3, c4, c5, c6, c7;
                unpack2(acc[i][0], c0, c1);
                unpack2(acc[i][1], c2, c3);
                unpack2(acc[i][2], c4, c5);
                unpack2(acc[i][3], c6, c7);
                float4 o0 = make_float4(fmaxf(c0 + bb0.x, 0.f), fmaxf(c1 + bb0.y, 0.f),
                                        fmaxf(c2 + bb0.z, 0.f), fmaxf(c3 + bb0.w, 0.f));
                float4 o1 = make_float4(fmaxf(c4 + bb1.x, 0.f), fmaxf(c5 + bb1.y, 0.f),
                                        fmaxf(c6 + bb1.z, 0.f), fmaxf(c7 + bb1.w, 0.f));
                float* cp = C + (size_t)row * D_HID + bn + tx * 4;
                *(float4*)cp = o0;
                *(float4*)(cp + 64) = o1;
            }
        }
    }
}

// ---------------- the mega kernel ----------------
__global__ __launch_bounds__(NT, 2) void mega_kernel(
    const float* __restrict__ x, const void* __restrict__ ei, const void* __restrict__ bt,
    const float* __restrict__ W1_root, const float* __restrict__ W1_rel, const float* __restrict__ b1,
    const float* __restrict__ W2_root, const float* __restrict__ W2_rel, const float* __restrict__ b2,
    const float* __restrict__ Wfc, const float* __restrict__ bfc, float* __restrict__ out) {
    __shared__ SmemAll sm;
    const int b = blockIdx.x, t = threadIdx.x;
    const int nb = gridDim.x;
    int epoch = 0;

    const int i64 = g_idx64;   // set by reset_kernel

    // A: histogram of in-degrees (g_cnt zeroed by reset_kernel)
    for (int i = b * NT + t; i < N_EDGES; i += nb * NT) {
        int d = load_idx_(ei, i + N_EDGES, i64);
        atomicAdd(&g_cnt[d], 1);
    }
    gridbar(++epoch * nb);

    // B: exclusive scan -> g_row / g_cur
    {
        const int CHUNK = (N_NODES + nb - 1) / nb;
        int base = b * CHUNK;
        int lim = base + CHUNK; if (lim > N_NODES) lim = N_NODES;
        int i0 = base + t * 2, i1 = i0 + 1;
        int v0 = (i0 < lim) ? g_cnt[i0] : 0;
        int v1 = (i1 < lim) ? g_cnt[i1] : 0;
        int total;
        int ex = block_scan_excl(v0 + v1, sm.s, total);
        if (t == 0) g_bagg[b] = total;
        gridbar(++epoch * nb);
        if (b == 0) {
            int j0 = t * 2, j1 = j0 + 1;
            int w0 = (j0 < nb) ? g_bagg[j0] : 0;
            int w1 = (j1 < nb) ? g_bagg[j1] : 0;
            int btot;
            int bex = block_scan_excl(w0 + w1, sm.s, btot);
            if (j0 < nb) g_bpref[j0] = bex;
            if (j1 < nb) g_bpref[j1] = bex + w0;
        }
        gridbar(++epoch * nb);
        int off = g_bpref[b];
        if (i0 < lim) { int r = off + ex;      g_row[i0] = r; g_cur[i0] = r; }
        if (i1 < lim) { int r = off + ex + v0; g_row[i1] = r; g_cur[i1] = r; }
        if (b == 0 && t == 0) g_row[N_NODES] = N_EDGES;
    }
    gridbar(++epoch * nb);

    // C: CSR fill
    for (int i = b * NT + t; i < N_EDGES; i += nb * NT) {
        int s = load_idx_(ei, i, i64);
        int d = load_idx_(ei, i + N_EDGES, i64);
        g_col[atomicAdd(&g_cur[d], 1)] = s;
    }
    gridbar(++epoch * nb);

    // D: gather layer 1 (warp work-stealing, MLP-8)
    gather_stage<32>(&g_wq[2], N_CH_L1, x, g_agg1);
    gridbar(++epoch * nb);

    // E: dual GEMM layer 1
    gemm_stage<D_IN>(x, W1_root, g_agg1, W1_rel, b1, g_h1, sm.g, &g_wq[0]);
    gridbar(++epoch * nb);

    // F: gather layer 2 (warp work-stealing over half-row segments, MLP-8)
    gather_stage<64>(&g_wq[3], N_CH_L2, g_h1, g_agg2);
    gridbar(++epoch * nb);

    // G: dual GEMM layer 2
    gemm_stage<D_HID>(g_h1, W2_root, g_agg2, W2_rel, b2, g_h2, sm.g, &g_wq[1]);
    gridbar(++epoch * nb);

    // H: mean-pool + FC + sigmoid (batch sorted -> contiguous segments)
    for (int g = b; g < N_GRAPHS; g += nb) {
        __syncthreads();
        int start, end;
        {
            int lo = 0, hi = N_NODES;
            while (lo < hi) { int mid = (lo + hi) >> 1; if (load_idx_(bt, mid, i64) < g) lo = mid + 1; else hi = mid; }
            start = lo;
            lo = start; hi = N_NODES;
            while (lo < hi) { int mid = (lo + hi) >> 1; if (load_idx_(bt, mid, i64) < g + 1) lo = mid + 1; else hi = mid; }
            end = lo;
        }
        float s0 = 0.f, s1 = 0.f, s2 = 0.f, s3 = 0.f;
        int n = start;
        for (; n + 4 <= end; n += 4) {
            s0 += g_h2[(size_t)(n + 0) * D_HID + t];
            s1 += g_h2[(size_t)(n + 1) * D_HID + t];
            s2 += g_h2[(size_t)(n + 2) * D_HID + t];
            s3 += g_h2[(size_t)(n + 3) * D_HID + t];
        }
        for (; n < end; n++) s0 += g_h2[(size_t)n * D_HID + t];
        float s = (s0 + s1) + (s2 + s3);
        float p = s / fmaxf((float)(end - start), 1.0f);
        sm.p.r0[t] = p * Wfc[t];
        sm.p.r1[t] = p * Wfc[D_HID + t];
        __syncthreads();
        for (int off = 128; off > 0; off >>= 1) {
            if (t < off) { sm.p.r0[t] += sm.p.r0[t + off]; sm.p.r1[t] += sm.p.r1[t + off]; }
            __syncthreads();
        }
        if (t == 0) {
            out[g * 2 + 0] = 1.0f / (1.0f + expf(-(sm.p.r0[0] + bfc[0])));
            out[g * 2 + 1] = 1.0f / (1.0f + expf(-(sm.p.r1[0] + bfc[1])));
        }
    }
}

// ---------------- launch ----------------
extern "C" void kernel_launch(void* const* d_in, const int* in_sizes, int n_in,
                              void* d_out, int out_size) {
    const float* x  = (const float*)d_in[0];
    const void*  ei = d_in[1];
    const void*  bt = d_in[2];
    int wbase = (n_in >= 12 && in_sizes[3] == 1) ? 4 : 3;
    const float* W1_root = (const float*)d_in[wbase + 0];
    const float* W1_rel  = (const float*)d_in[wbase + 1];
    const float* b1      = (const float*)d_in[wbase + 2];
    const float* W2_root = (const float*)d_in[wbase + 3];
    const float* W2_rel  = (const float*)d_in[wbase + 4];
    const float* b2      = (const float*)d_in[wbase + 5];
    const float* Wfc     = (const float*)d_in[wbase + 6];
    const float* bfc     = (const float*)d_in[wbase + 7];
    float* out = (float*)d_out;

    int occ = 1;
    cudaOccupancyMaxActiveBlocksPerMultiprocessor(&occ, mega_kernel, NT, 0);
    if (occ < 1) occ = 1;
    if (occ > 2) occ = 2;
    int nb = 148 * occ;

    reset_kernel<<<256, 256>>>((const int*)ei);
    mega_kernel<<<nb, NT>>>(x, ei, bt, W1_root, W1_rel, b1,
                            W2_root, W2_rel, b2, Wfc, bfc, out);
    (void)out_size;
}

// round 15
// speedup vs baseline: 1.0341x; 1.0341x over previous
#include <cuda_runtime.h>
#include <cstdint>

#define N_NODES  50000
#define N_EDGES  800000
#define D_IN     128
#define D_HID    256
#define N_GRAPHS 256
#define NT       256

#define N_MTILES ((N_NODES + 127) / 128)       // 391
#define N_GT     (N_MTILES * 2)                // 782 gemm tiles
#define N_CH8    (N_NODES / 8)                 // 6250 gather chunks of 8 nodes

typedef unsigned long long ull;

// ---------------- scratch (device globals; no runtime allocation) ----------------
__device__ float g_agg1[N_NODES * D_IN];
__device__ float g_h1  [N_NODES * D_HID];
__device__ float g_agg2[N_NODES * D_HID];
__device__ float g_h2  [N_NODES * D_HID];
__device__ int   g_cnt [N_NODES];
__device__ int   g_row [N_NODES + 1];
__device__ int   g_cur [N_NODES];
__device__ int   g_col [N_EDGES];
__device__ int   g_bagg[512];
__device__ int   g_bpref[512];
__device__ int   g_barrier_ctr;
__device__ int   g_wq[4];
__device__ int   g_idx64;

// ---------------- packed f32x2 helpers ----------------
__device__ __forceinline__ ull pack2(float lo, float hi) {
    ull r;
    asm("mov.b64 %0, {%1, %2};" : "=l"(r) : "f"(lo), "f"(hi));
    return r;
}
__device__ __forceinline__ void unpack2(ull v, float& lo, float& hi) {
    asm("mov.b64 {%0, %1}, %2;" : "=f"(lo), "=f"(hi) : "l"(v));
}
__device__ __forceinline__ ull fma2(ull a, ull b, ull c) {
    ull r;
    asm("fma.rn.f32x2 %0, %1, %2, %3;" : "=l"(r) : "l"(a), "l"(b), "l"(c));
    return r;
}

__device__ __forceinline__ int load_idx_(const void* p, int i, int i64) {
    if (i64) return (int)((const long long*)p)[i];
    return ((const int*)p)[i];
}

// ---------------- shared memory union ----------------
struct SmemGemm { float As[2][16][132]; float Bs[2][16][132]; int tile; };
struct SmemScan { int wsum[32]; };
struct SmemPool { float r0[NT]; float r1[NT]; };
union SmemAll { SmemGemm g; SmemScan s; SmemPool p; };

// ---------------- grid barrier (all gridDim.x blocks resident) --------------------
__device__ __forceinline__ void gridbar(int target) {
    __syncthreads();
    if (threadIdx.x == 0) {
        __threadfence();
        atomicAdd(&g_barrier_ctr, 1);
        while (*(volatile int*)&g_barrier_ctr < target) { __nanosleep(64); }
    }
    __syncthreads();
}

// ---------------- prep kernel ----------------
__global__ void reset_kernel(const int* __restrict__ ei) {
    int i = blockIdx.x * blockDim.x + threadIdx.x;
    if (i == 0) {
        g_barrier_ctr = 0;
#pragma unroll
        for (int q = 0; q < 4; q++) g_wq[q] = 0;
        int any = 0;
#pragma unroll
        for (int j = 1; j < 256; j += 2) any |= ei[j];
        g_idx64 = (any == 0) ? 1 : 0;
    }
    for (; i < N_NODES; i += gridDim.x * blockDim.x) g_cnt[i] = 0;
}

// ---------------- block-wide exclusive scan over 256 thread values ----------------
__device__ int block_scan_excl(int v, SmemScan& ss, int& total) {
    int lane = threadIdx.x & 31, w = threadIdx.x >> 5;
    int s = v;
#pragma unroll
    for (int o = 1; o < 32; o <<= 1) {
        int u = __shfl_up_sync(0xffffffffu, s, o);
        if (lane >= o) s += u;
    }
    if (lane == 31) ss.wsum[w] = s;
    __syncthreads();
    if (w == 0) {
        int ws = (lane < 8) ? ss.wsum[lane] : 0;
#pragma unroll
        for (int o = 1; o < 8; o <<= 1) {
            int u = __shfl_up_sync(0xffffffffu, ws, o);
            if (lane >= o) ws += u;
        }
        if (lane < 8) ss.wsum[lane] = ws;
    }
    __syncthreads();
    int incl = s + (w > 0 ? ss.wsum[w - 1] : 0);
    total = ss.wsum[7];
    return incl - v;
}

// ---------------- D=128 gather: one node per warp-job, batch-8 (MLP 8) ------------
__device__ __forceinline__ void gather_node128(int node, const float* __restrict__ x,
                                               float* __restrict__ agg, int lane) {
    int beg = g_row[node], end = g_row[node + 1];
    const float4* xb = (const float4*)x;
    float4 a = make_float4(0.f, 0.f, 0.f, 0.f);

    int p = beg;
    int c[8];
    if (p + 8 <= end) {
#pragma unroll
        for (int i = 0; i < 8; i++) c[i] = g_col[p + i];
    }
    while (p + 8 <= end) {
        int n0 = c[0], n1 = c[1], n2 = c[2], n3 = c[3];
        int n4 = c[4], n5 = c[5], n6 = c[6], n7 = c[7];
        int pn = p + 8;
        if (pn + 8 <= end) {
#pragma unroll
            for (int i = 0; i < 8; i++) c[i] = g_col[pn + i];
        }
        float4 v0 = xb[(size_t)n0 * 32 + lane];
        float4 v1 = xb[(size_t)n1 * 32 + lane];
        float4 v2 = xb[(size_t)n2 * 32 + lane];
        float4 v3 = xb[(size_t)n3 * 32 + lane];
        float4 v4 = xb[(size_t)n4 * 32 + lane];
        float4 v5 = xb[(size_t)n5 * 32 + lane];
        float4 v6 = xb[(size_t)n6 * 32 + lane];
        float4 v7 = xb[(size_t)n7 * 32 + lane];
        a.x += ((v0.x + v1.x) + (v2.x + v3.x)) + ((v4.x + v5.x) + (v6.x + v7.x));
        a.y += ((v0.y + v1.y) + (v2.y + v3.y)) + ((v4.y + v5.y) + (v6.y + v7.y));
        a.z += ((v0.z + v1.z) + (v2.z + v3.z)) + ((v4.z + v5.z) + (v6.z + v7.z));
        a.w += ((v0.w + v1.w) + (v2.w + v3.w)) + ((v4.w + v5.w) + (v6.w + v7.w));
        p = pn;
    }
    if (p + 4 <= end) {
        int n0 = g_col[p], n1 = g_col[p + 1], n2 = g_col[p + 2], n3 = g_col[p + 3];
        float4 v0 = xb[(size_t)n0 * 32 + lane];
        float4 v1 = xb[(size_t)n1 * 32 + lane];
        float4 v2 = xb[(size_t)n2 * 32 + lane];
        float4 v3 = xb[(size_t)n3 * 32 + lane];
        a.x += (v0.x + v1.x) + (v2.x + v3.x);
        a.y += (v0.y + v1.y) + (v2.y + v3.y);
        a.z += (v0.z + v1.z) + (v2.z + v3.z);
        a.w += (v0.w + v1.w) + (v2.w + v3.w);
        p += 4;
    }
    for (; p < end; p++) {
        int s0 = g_col[p];
        float4 v0 = xb[(size_t)s0 * 32 + lane];
        a.x += v0.x; a.y += v0.y; a.z += v0.z; a.w += v0.w;
    }
    ((float4*)agg)[(size_t)node * 32 + lane] = a;
}

// ---------------- D=256 gather: batch-4 x V=2 (8 loads in flight) -----------------
__device__ __forceinline__ void gather_node256(int node, const float* __restrict__ x,
                                               float* __restrict__ agg, int lane) {
    int beg = g_row[node], end = g_row[node + 1];
    float4 a0 = make_float4(0.f, 0.f, 0.f, 0.f);
    float4 a1 = make_float4(0.f, 0.f, 0.f, 0.f);

    int p = beg;
    int c0 = 0, c1 = 0, c2 = 0, c3 = 0;
    if (p + 4 <= end) {
        c0 = g_col[p]; c1 = g_col[p + 1]; c2 = g_col[p + 2]; c3 = g_col[p + 3];
    }
    while (p + 4 <= end) {
        int n0 = c0, n1 = c1, n2 = c2, n3 = c3;
        int pn = p + 4;
        if (pn + 4 <= end) {
            c0 = g_col[pn]; c1 = g_col[pn + 1]; c2 = g_col[pn + 2]; c3 = g_col[pn + 3];
        }
        const float4* x0 = (const float4*)x + (size_t)n0 * 64;
        const float4* x1 = (const float4*)x + (size_t)n1 * 64;
        const float4* x2 = (const float4*)x + (size_t)n2 * 64;
        const float4* x3 = (const float4*)x + (size_t)n3 * 64;
        float4 u0 = x0[lane],      w0 = x0[lane + 32];
        float4 u1 = x1[lane],      w1 = x1[lane + 32];
        float4 u2 = x2[lane],      w2 = x2[lane + 32];
        float4 u3 = x3[lane],      w3 = x3[lane + 32];
        a0.x += (u0.x + u1.x) + (u2.x + u3.x);
        a0.y += (u0.y + u1.y) + (u2.y + u3.y);
        a0.z += (u0.z + u1.z) + (u2.z + u3.z);
        a0.w += (u0.w + u1.w) + (u2.w + u3.w);
        a1.x += (w0.x + w1.x) + (w2.x + w3.x);
        a1.y += (w0.y + w1.y) + (w2.y + w3.y);
        a1.z += (w0.z + w1.z) + (w2.z + w3.z);
        a1.w += (w0.w + w1.w) + (w2.w + w3.w);
        p = pn;
    }
    for (; p < end; p++) {
        int s0 = g_col[p];
        const float4* x0 = (const float4*)x + (size_t)s0 * 64;
        float4 u0 = x0[lane], w0 = x0[lane + 32];
        a0.x += u0.x; a0.y += u0.y; a0.z += u0.z; a0.w += u0.w;
        a1.x += w0.x; a1.y += w0.y; a1.z += w0.z; a1.w += w0.w;
    }
    float4* ap = (float4*)agg + (size_t)node * 64;
    ap[lane] = a0;
    ap[lane + 32] = a1;
}

// ---------------- gather stages: warp-granular work stealing ----------------------
template<int D>
__device__ void gather_stage(int* wq, const float* __restrict__ x, float* __restrict__ agg) {
    int lane = threadIdx.x & 31;
    while (true) {
        int ch;
        if (lane == 0) ch = atomicAdd(wq, 1);
        ch = __shfl_sync(0xffffffffu, ch, 0);
        if (ch >= N_CH8) break;
        int base = ch * 8;
#pragma unroll 1
        for (int k = 0; k < 8; k++) {
            if (D == 128) gather_node128(base + k, x, agg, lane);
            else          gather_node256(base + k, x, agg, lane);
        }
    }
}

// ---------------- gemm stage: C = relu(A1@W1^T + A2@W2^T + bias) ------------------
// 128x128 tiles, BK=16, f32x2 packed FMA, work-stealing tile scheduler.
template<int K>
__device__ void gemm_stage(const float* __restrict__ A1, const float* __restrict__ W1,
                           const float* __restrict__ A2, const float* __restrict__ W2,
                           const float* __restrict__ bias, float* __restrict__ C,
                           SmemGemm& sm, int* wq) {
    constexpr int BK = 16;
    constexpr int T = K / BK;
    int tid = threadIdx.x;
    int tx = tid & 15;
    int ty = tid >> 4;
    int lm = tid >> 2;
    int lk = (tid & 3) * 4;
    const float4 z4 = make_float4(0.f, 0.f, 0.f, 0.f);

    while (true) {
        if (tid == 0) sm.tile = atomicAdd(wq, 1);
        __syncthreads();
        int tile = sm.tile;
        if (tile >= N_GT) break;
        int bm = (tile >> 1) * 128;
        int bn = (tile & 1) * 128;

        ull acc[8][4];
#pragma unroll
        for (int i = 0; i < 8; i++)
#pragma unroll
            for (int j = 0; j < 4; j++) acc[i][j] = pack2(0.f, 0.f);

#pragma unroll 1
        for (int phase = 0; phase < 2; phase++) {
            const float* A = phase ? A2 : A1;
            const float* W = phase ? W2 : W1;

            float4 ra0, ra1, rb0, rb1;
            {
                int r0 = bm + lm, r1 = bm + lm + 64;
                ra0 = (r0 < N_NODES) ? *(const float4*)(A + (size_t)r0 * K + lk) : z4;
                ra1 = (r1 < N_NODES) ? *(const float4*)(A + (size_t)r1 * K + lk) : z4;
                rb0 = *(const float4*)(W + (size_t)(bn + lm) * K + lk);
                rb1 = *(const float4*)(W + (size_t)(bn + lm + 64) * K + lk);
                sm.As[0][lk + 0][lm] = ra0.x; sm.As[0][lk + 1][lm] = ra0.y;
                sm.As[0][lk + 2][lm] = ra0.z; sm.As[0][lk + 3][lm] = ra0.w;
                sm.As[0][lk + 0][lm + 64] = ra1.x; sm.As[0][lk + 1][lm + 64] = ra1.y;
                sm.As[0][lk + 2][lm + 64] = ra1.z; sm.As[0][lk + 3][lm + 64] = ra1.w;
                sm.Bs[0][lk + 0][lm] = rb0.x; sm.Bs[0][lk + 1][lm] = rb0.y;
                sm.Bs[0][lk + 2][lm] = rb0.z; sm.Bs[0][lk + 3][lm] = rb0.w;
                sm.Bs[0][lk + 0][lm + 64] = rb1.x; sm.Bs[0][lk + 1][lm + 64] = rb1.y;
                sm.Bs[0][lk + 2][lm + 64] = rb1.z; sm.Bs[0][lk + 3][lm + 64] = rb1.w;
            }
            __syncthreads();

#pragma unroll 1
            for (int t = 0; t < T; t++) {
                int cur = t & 1, nxt = cur ^ 1;
                if (t + 1 < T) {
                    int k0 = (t + 1) * BK;
                    int r0 = bm + lm, r1 = bm + lm + 64;
                    ra0 = (r0 < N_NODES) ? *(const float4*)(A + (size_t)r0 * K + k0 + lk) : z4;
                    ra1 = (r1 < N_NODES) ? *(const float4*)(A + (size_t)r1 * K + k0 + lk) : z4;
                    rb0 = *(const float4*)(W + (size_t)(bn + lm) * K + k0 + lk);
                    rb1 = *(const float4*)(W + (size_t)(bn + lm + 64) * K + k0 + lk);
                }
#pragma unroll
                for (int k = 0; k < BK; k++) {
                    float4 av0 = *(const float4*)&sm.As[cur][k][ty * 8];
                    float4 av1 = *(const float4*)&sm.As[cur][k][ty * 8 + 4];
                    float4 bv0 = *(const float4*)&sm.Bs[cur][k][tx * 4];
                    float4 bv1 = *(const float4*)&sm.Bs[cur][k][64 + tx * 4];
                    ull b0 = pack2(bv0.x, bv0.y);
                    ull b1 = pack2(bv0.z, bv0.w);
                    ull b2 = pack2(bv1.x, bv1.y);
                    ull b3 = pack2(bv1.z, bv1.w);
                    ull ad;
                    ad = pack2(av0.x, av0.x);
                    acc[0][0] = fma2(ad, b0, acc[0][0]); acc[0][1] = fma2(ad, b1, acc[0][1]);
                    acc[0][2] = fma2(ad, b2, acc[0][2]); acc[0][3] = fma2(ad, b3, acc[0][3]);
                    ad = pack2(av0.y, av0.y);
                    acc[1][0] = fma2(ad, b0, acc[1][0]); acc[1][1] = fma2(ad, b1, acc[1][1]);
                    acc[1][2] = fma2(ad, b2, acc[1][2]); acc[1][3] = fma2(ad, b3, acc[1][3]);
                    ad = pack2(av0.z, av0.z);
                    acc[2][0] = fma2(ad, b0, acc[2][0]); acc[2][1] = fma2(ad, b1, acc[2][1]);
                    acc[2][2] = fma2(ad, b2, acc[2][2]); acc[2][3] = fma2(ad, b3, acc[2][3]);
                    ad = pack2(av0.w, av0.w);
                    acc[3][0] = fma2(ad, b0, acc[3][0]); acc[3][1] = fma2(ad, b1, acc[3][1]);
                    acc[3][2] = fma2(ad, b2, acc[3][2]); acc[3][3] = fma2(ad, b3, acc[3][3]);
                    ad = pack2(av1.x, av1.x);
                    acc[4][0] = fma2(ad, b0, acc[4][0]); acc[4][1] = fma2(ad, b1, acc[4][1]);
                    acc[4][2] = fma2(ad, b2, acc[4][2]); acc[4][3] = fma2(ad, b3, acc[4][3]);
                    ad = pack2(av1.y, av1.y);
                    acc[5][0] = fma2(ad, b0, acc[5][0]); acc[5][1] = fma2(ad, b1, acc[5][1]);
                    acc[5][2] = fma2(ad, b2, acc[5][2]); acc[5][3] = fma2(ad, b3, acc[5][3]);
                    ad = pack2(av1.z, av1.z);
                    acc[6][0] = fma2(ad, b0, acc[6][0]); acc[6][1] = fma2(ad, b1, acc[6][1]);
                    acc[6][2] = fma2(ad, b2, acc[6][2]); acc[6][3] = fma2(ad, b3, acc[6][3]);
                    ad = pack2(av1.w, av1.w);
                    acc[7][0] = fma2(ad, b0, acc[7][0]); acc[7][1] = fma2(ad, b1, acc[7][1]);
                    acc[7][2] = fma2(ad, b2, acc[7][2]); acc[7][3] = fma2(ad, b3, acc[7][3]);
                }
                if (t + 1 < T) {
                    sm.As[nxt][lk + 0][lm] = ra0.x; sm.As[nxt][lk + 1][lm] = ra0.y;
                    sm.As[nxt][lk + 2][lm] = ra0.z; sm.As[nxt][lk + 3][lm] = ra0.w;
                    sm.As[nxt][lk + 0][lm + 64] = ra1.x; sm.As[nxt][lk + 1][lm + 64] = ra1.y;
                    sm.As[nxt][lk + 2][lm + 64] = ra1.z; sm.As[nxt][lk + 3][lm + 64] = ra1.w;
                    sm.Bs[nxt][lk + 0][lm] = rb0.x; sm.Bs[nxt][lk + 1][lm] = rb0.y;
                    sm.Bs[nxt][lk + 2][lm] = rb0.z; sm.Bs[nxt][lk + 3][lm] = rb0.w;
                    sm.Bs[nxt][lk + 0][lm + 64] = rb1.x; sm.Bs[nxt][lk + 1][lm + 64] = rb1.y;
                    sm.Bs[nxt][lk + 2][lm + 64] = rb1.z; sm.Bs[nxt][lk + 3][lm + 64] = rb1.w;
                }
                __syncthreads();
            }
            __syncthreads();
        }

        // epilogue: bias + relu
        float4 bb0 = *(const float4*)(bias + bn + tx * 4);
        float4 bb1 = *(const float4*)(bias + bn + 64 + tx * 4);
#pragma unroll
        for (int i = 0; i < 8; i++) {
            int row = bm + ty * 8 + i;
            if (row < N_NODES) {
                float c0, c1, c2, c3, c4, c5, c6, c7;
                unpack2(acc[i][0], c0, c1);
                unpack2(acc[i][1], c2, c3);
                unpack2(acc[i][2], c4, c5);
                unpack2(acc[i][3], c6, c7);
                float4 o0 = make_float4(fmaxf(c0 + bb0.x, 0.f), fmaxf(c1 + bb0.y, 0.f),
                                        fmaxf(c2 + bb0.z, 0.f), fmaxf(c3 + bb0.w, 0.f));
                float4 o1 = make_float4(fmaxf(c4 + bb1.x, 0.f), fmaxf(c5 + bb1.y, 0.f),
                                        fmaxf(c6 + bb1.z, 0.f), fmaxf(c7 + bb1.w, 0.f));
                float* cp = C + (size_t)row * D_HID + bn + tx * 4;
                *(float4*)cp = o0;
                *(float4*)(cp + 64) = o1;
            }
        }
    }
}

// ---------------- the mega kernel ----------------
__global__ __launch_bounds__(NT, 2) void mega_kernel(
    const float* __restrict__ x, const void* __restrict__ ei, const void* __restrict__ bt,
    const float* __restrict__ W1_root, const float* __restrict__ W1_rel, const float* __restrict__ b1,
    const float* __restrict__ W2_root, const float* __restrict__ W2_rel, const float* __restrict__ b2,
    const float* __restrict__ Wfc, const float* __restrict__ bfc, float* __restrict__ out) {
    __shared__ SmemAll sm;
    const int b = blockIdx.x, t = threadIdx.x;
    const int nb = gridDim.x;
    int epoch = 0;

    const int i64 = g_idx64;   // set by reset_kernel

    // A: histogram of in-degrees (g_cnt zeroed by reset_kernel)
    for (int i = b * NT + t; i < N_EDGES; i += nb * NT) {
        int d = load_idx_(ei, i + N_EDGES, i64);
        atomicAdd(&g_cnt[d], 1);
    }
    gridbar(++epoch * nb);

    // B: exclusive scan -> g_row / g_cur
    {
        const int CHUNK = (N_NODES + nb - 1) / nb;
        int base = b * CHUNK;
        int lim = base + CHUNK; if (lim > N_NODES) lim = N_NODES;
        int i0 = base + t * 2, i1 = i0 + 1;
        int v0 = (i0 < lim) ? g_cnt[i0] : 0;
        int v1 = (i1 < lim) ? g_cnt[i1] : 0;
        int total;
        int ex = block_scan_excl(v0 + v1, sm.s, total);
        if (t == 0) g_bagg[b] = total;
        gridbar(++epoch * nb);
        if (b == 0) {
            int j0 = t * 2, j1 = j0 + 1;
            int w0 = (j0 < nb) ? g_bagg[j0] : 0;
            int w1 = (j1 < nb) ? g_bagg[j1] : 0;
            int btot;
            int bex = block_scan_excl(w0 + w1, sm.s, btot);
            if (j0 < nb) g_bpref[j0] = bex;
            if (j1 < nb) g_bpref[j1] = bex + w0;
        }
        gridbar(++epoch * nb);
        int off = g_bpref[b];
        if (i0 < lim) { int r = off + ex;      g_row[i0] = r; g_cur[i0] = r; }
        if (i1 < lim) { int r = off + ex + v0; g_row[i1] = r; g_cur[i1] = r; }
        if (b == 0 && t == 0) g_row[N_NODES] = N_EDGES;
    }
    gridbar(++epoch * nb);

    // C: CSR fill
    for (int i = b * NT + t; i < N_EDGES; i += nb * NT) {
        int s = load_idx_(ei, i, i64);
        int d = load_idx_(ei, i + N_EDGES, i64);
        g_col[atomicAdd(&g_cur[d], 1)] = s;
    }
    gridbar(++epoch * nb);

    // D: gather layer 1 (warp work-stealing, batch-8, MLP 8)
    gather_stage<D_IN>(&g_wq[2], x, g_agg1);
    gridbar(++epoch * nb);

    // E: dual GEMM layer 1
    gemm_stage<D_IN>(x, W1_root, g_agg1, W1_rel, b1, g_h1, sm.g, &g_wq[0]);
    gridbar(++epoch * nb);

    // F: gather layer 2 (warp work-stealing, batch-4 x V=2, MLP 8)
    gather_stage<D_HID>(&g_wq[3], g_h1, g_agg2);
    gridbar(++epoch * nb);

    // G: dual GEMM layer 2
    gemm_stage<D_HID>(g_h1, W2_root, g_agg2, W2_rel, b2, g_h2, sm.g, &g_wq[1]);
    gridbar(++epoch * nb);

    // H: mean-pool + FC + sigmoid (batch sorted -> contiguous segments)
    for (int g = b; g < N_GRAPHS; g += nb) {
        __syncthreads();
        int start, end;
        {
            int lo = 0, hi = N_NODES;
            while (lo < hi) { int mid = (lo + hi) >> 1; if (load_idx_(bt, mid, i64) < g) lo = mid + 1; else hi = mid; }
            start = lo;
            lo = start; hi = N_NODES;
            while (lo < hi) { int mid = (lo + hi) >> 1; if (load_idx_(bt, mid, i64) < g + 1) lo = mid + 1; else hi = mid; }
            end = lo;
        }
        float s0 = 0.f, s1 = 0.f, s2 = 0.f, s3 = 0.f;
        int n = start;
        for (; n + 4 <= end; n += 4) {
            s0 += g_h2[(size_t)(n + 0) * D_HID + t];
            s1 += g_h2[(size_t)(n + 1) * D_HID + t];
            s2 += g_h2[(size_t)(n + 2) * D_HID + t];
            s3 += g_h2[(size_t)(n + 3) * D_HID + t];
        }
        for (; n < end; n++) s0 += g_h2[(size_t)n * D_HID + t];
        float s = (s0 + s1) + (s2 + s3);
        float p = s / fmaxf((float)(end - start), 1.0f);
        sm.p.r0[t] = p * Wfc[t];
        sm.p.r1[t] = p * Wfc[D_HID + t];
        __syncthreads();
        for (int off = 128; off > 0; off >>= 1) {
            if (t < off) { sm.p.r0[t] += sm.p.r0[t + off]; sm.p.r1[t] += sm.p.r1[t + off]; }
            __syncthreads();
        }
        if (t == 0) {
            out[g * 2 + 0] = 1.0f / (1.0f + expf(-(sm.p.r0[0] + bfc[0])));
            out[g * 2 + 1] = 1.0f / (1.0f + expf(-(sm.p.r1[0] + bfc[1])));
        }
    }
}

// ---------------- launch ----------------
extern "C" void kernel_launch(void* const* d_in, const int* in_sizes, int n_in,
                              void* d_out, int out_size) {
    const float* x  = (const float*)d_in[0];
    const void*  ei = d_in[1];
    const void*  bt = d_in[2];
    int wbase = (n_in >= 12 && in_sizes[3] == 1) ? 4 : 3;
    const float* W1_root = (const float*)d_in[wbase + 0];
    const float* W1_rel  = (const float*)d_in[wbase + 1];
    const float* b1      = (const float*)d_in[wbase + 2];
    const float* W2_root = (const float*)d_in[wbase + 3];
    const float* W2_rel  = (const float*)d_in[wbase + 4];
    const float* b2      = (const float*)d_in[wbase + 5];
    const float* Wfc     = (const float*)d_in[wbase + 6];
    const float* bfc     = (const float*)d_in[wbase + 7];
    float* out = (float*)d_out;

    int occ = 1;
    cudaOccupancyMaxActiveBlocksPerMultiprocessor(&occ, mega_kernel, NT, 0);
    if (occ < 1) occ = 1;
    if (occ > 2) occ = 2;
    int nb = 148 * occ;

    reset_kernel<<<256, 256>>>((const int*)ei);
    mega_kernel<<<nb, NT>>>(x, ei, bt, W1_root, W1_rel, b1,
                            W2_root, W2_rel, b2, Wfc, bfc, out);
    (void)out_size;
}